// round 3
// baseline (speedup 1.0000x reference)
#include <cuda_runtime.h>
#include <cuda_bf16.h>
#include <cstdint>
#include <cstddef>

#define NB 64
#define NH 12
#define NP 197
#define ND 64
#define TOPK 10
#define NSLOT 7
#define FULLMASK 0xffffffffu

// Persistent device state (statically initialized; last block resets -> replay-safe)
__device__ double g_acc = 0.0;
__device__ unsigned g_done = 0;

// float -> order-preserving u32 key, low 8 bits replaced by source index.
// Monotone in f up to a <=256-ulp perturbation (3e-5 relative): acceptable.
__device__ __forceinline__ unsigned key_pack(float f, unsigned idx) {
    int u = __float_as_int(f);
    unsigned mask = ((unsigned)(u >> 31)) | 0x80000000u;
    return (((unsigned)u ^ mask) & 0xFFFFFF00u) | idx;
}
__device__ __forceinline__ float key2f(unsigned k) {
    unsigned mask = (unsigned)(~(((int)k) >> 31)) | 0x80000000u;
    return __int_as_float((int)(k ^ mask));
}

// descending compare-exchange (2x IMNMX.U32)
__device__ __forceinline__ void ce(unsigned& a, unsigned& b) {
    unsigned mx = a > b ? a : b;
    unsigned mn = a > b ? b : a;
    a = mx; b = mn;
}
// Batcher odd-even mergesort for 8 with element 7 = constant-min -> 16-CE sort-7.
__device__ __forceinline__ void sort7(unsigned s[NSLOT]) {
    ce(s[0],s[1]); ce(s[2],s[3]); ce(s[4],s[5]);
    ce(s[0],s[2]); ce(s[1],s[3]); ce(s[4],s[6]);
    ce(s[1],s[2]); ce(s[5],s[6]);
    ce(s[0],s[4]); ce(s[1],s[5]); ce(s[2],s[6]);
    ce(s[2],s[4]); ce(s[3],s[5]);
    ce(s[1],s[2]); ce(s[3],s[4]); ce(s[5],s[6]);
}

__device__ __forceinline__ void load_row(float y[NSLOT], const float* __restrict__ row,
                                         int lane) {
    const float NEG_INF = __int_as_float(0xff800000);
#pragma unroll
    for (int k = 0; k < 6; ++k) y[k] = row[k * 32 + lane];
    y[6] = (lane < NP - 192) ? row[192 + lane] : NEG_INF;
}

// unpack bf16x2 (lo = d even, hi = d odd) via shift trick -- no CVT pipe.
__device__ __forceinline__ float2 bf2_unpack(unsigned w) {
    return make_float2(__uint_as_float(w << 16),
                       __uint_as_float(w & 0xFFFF0000u));
}

__global__ void __launch_bounds__(256, 3)
hintop_main(const float* __restrict__ att_s, const float* __restrict__ att_t,
            const float* __restrict__ v_s,   const float* __restrict__ v_t,
            float* __restrict__ out) {
    extern __shared__ unsigned smem_v[];        // [2][NP*ND/2] bf16x2 (50,432 B)
    const int bh = blockIdx.x;                  // (b*H + h), 0..767
    const int warp = threadIdx.x >> 5;
    const int lane = threadIdx.x & 31;

    unsigned* vsS = smem_v;                     // NP*ND/2 = 6304 u32
    unsigned* vsT = smem_v + NP * ND / 2;
    {
        const float4* a4 = reinterpret_cast<const float4*>(v_s + (size_t)bh * NP * ND);
        const float4* b4 = reinterpret_cast<const float4*>(v_t + (size_t)bh * NP * ND);
        uint2* s2 = reinterpret_cast<uint2*>(vsS);
        uint2* t2 = reinterpret_cast<uint2*>(vsT);
        for (int i = threadIdx.x; i < NP * ND / 4; i += 256) {
            float4 a = a4[i];
            float4 b = b4[i];
            __nv_bfloat162 a0 = __floats2bfloat162_rn(a.x, a.y);
            __nv_bfloat162 a1 = __floats2bfloat162_rn(a.z, a.w);
            __nv_bfloat162 b0 = __floats2bfloat162_rn(b.x, b.y);
            __nv_bfloat162 b1 = __floats2bfloat162_rn(b.z, b.w);
            s2[i] = make_uint2(*(unsigned*)&a0, *(unsigned*)&a1);
            t2[i] = make_uint2(*(unsigned*)&b0, *(unsigned*)&b1);
        }
    }
    __syncthreads();

    const float* aS = att_s + (size_t)bh * NP * NP;
    const float* aT = att_t + (size_t)bh * NP * NP;
    // per-lane base: u32 element i*32+lane holds v[i][2*lane..2*lane+1] as bf16x2
    const unsigned* __restrict__ v2S = vsS + lane;
    const unsigned* __restrict__ v2T = vsT + lane;

    float lsum = 0.f;

    int p = warp;
    float cS[NSLOT], cT[NSLOT];
    if (p < NP) {
        load_row(cS, aS + (size_t)p * NP, lane);
        load_row(cT, aT + (size_t)p * NP, lane);
    }

    while (p < NP) {
        const int pn = p + 8;

        // Build packed keys and sort each lane's 7 descending (S,T interleaved).
        unsigned sS[NSLOT], sT[NSLOT];
#pragma unroll
        for (int k = 0; k < NSLOT; ++k) {
            unsigned idx = (unsigned)(k * 32 + lane);
            sS[k] = key_pack(cS[k], idx);
            sT[k] = key_pack(cT[k], idx);
        }
        sort7(sS);
        sort7(sT);

        // Prefetch next pair of rows: LDG latency overlaps sort+pop phase.
        float nS[NSLOT], nT[NSLOT];
        const bool more = (pn < NP);
        if (more) {
            load_row(nS, aS + (size_t)pn * NP, lane);
            load_row(nT, aT + (size_t)pn * NP, lane);
        }

        // Pop the warp-wide top-10; each pop yields (value,index) uniformly.
        float2 accS = make_float2(0.f, 0.f), accT = make_float2(0.f, 0.f);
        float wsS = 0.f, wsT = 0.f;
#pragma unroll
        for (int it = 0; it < TOPK; ++it) {
            unsigned wmS = __reduce_max_sync(FULLMASK, sS[0]);
            unsigned wmT = __reduce_max_sync(FULLMASK, sT[0]);

            if (it < TOPK - 1) {                // owner lane shifts its sorted list
                bool hS = (sS[0] == wmS);
#pragma unroll
                for (int k = 0; k < NSLOT - 1; ++k) sS[k] = hS ? sS[k + 1] : sS[k];
                sS[NSLOT - 1] = hS ? 0u : sS[NSLOT - 1];
                bool hT = (sT[0] == wmT);
#pragma unroll
                for (int k = 0; k < NSLOT - 1; ++k) sT[k] = hT ? sT[k + 1] : sT[k];
                sT[NSLOT - 1] = hT ? 0u : sT[NSLOT - 1];
            }

            unsigned iS = wmS & 0xFFu;          // packed index == k*32+lane
            unsigned iT = wmT & 0xFFu;
            float wS = __expf(key2f(wmS));      // normalizer cancels max-subtraction
            float wT = __expf(key2f(wmT));
            float2 vvS = bf2_unpack(v2S[iS * 32]);
            float2 vvT = bf2_unpack(v2T[iT * 32]);
            accS.x = fmaf(wS, vvS.x, accS.x);
            accS.y = fmaf(wS, vvS.y, accS.y);
            wsS += wS;
            accT.x = fmaf(wT, vvT.x, accT.x);
            accT.y = fmaf(wT, vvT.y, accT.y);
            wsT += wT;
        }

        float invS = __fdividef(1.0f, wsS);
        float invT = __fdividef(1.0f, wsT);
        float dx = accS.x * invS - accT.x * invT;
        float dy = accS.y * invS - accT.y * invT;
        lsum = fmaf(dx, dx, lsum);
        lsum = fmaf(dy, dy, lsum);

        p = pn;
        if (more) {
#pragma unroll
            for (int k = 0; k < NSLOT; ++k) { cS[k] = nS[k]; cT[k] = nT[k]; }
        }
    }

    // warp reduce -> block reduce -> one double atomic; last block finalizes.
#pragma unroll
    for (int off = 16; off; off >>= 1) lsum += __shfl_xor_sync(FULLMASK, lsum, off);

    __shared__ float wsum_sh[8];
    if (lane == 0) wsum_sh[warp] = lsum;
    __syncthreads();
    if (threadIdx.x == 0) {
        float t = 0.f;
#pragma unroll
        for (int w = 0; w < 8; ++w) t += wsum_sh[w];
        atomicAdd(&g_acc, (double)t);
        __threadfence();
        unsigned ticket = atomicAdd(&g_done, 1);
        if (ticket == (unsigned)(gridDim.x - 1)) {       // last block to finish
            __threadfence();
            double total = atomicAdd(&g_acc, 0.0);       // read via L2
            out[0] = (float)(total / (double)((size_t)NB * NH * NP * ND));
            g_acc = 0.0;                                 // reset for next replay
            g_done = 0;
            __threadfence();
        }
    }
}

extern "C" void kernel_launch(void* const* d_in, const int* in_sizes, int n_in,
                              void* d_out, int out_size) {
    const float* att_s = (const float*)d_in[0];
    const float* att_t = (const float*)d_in[1];
    const float* v_s   = (const float*)d_in[2];
    const float* v_t   = (const float*)d_in[3];

    const int smem_bytes = NP * ND * (int)sizeof(unsigned);   // 50,432 B (2 bf16 tiles)
    cudaFuncSetAttribute(hintop_main, cudaFuncAttributeMaxDynamicSharedMemorySize,
                         smem_bytes);

    hintop_main<<<NB * NH, 256, smem_bytes>>>(att_s, att_t, v_s, v_t, (float*)d_out);
}